// round 12
// baseline (speedup 1.0000x reference)
#include <cuda_runtime.h>
#include <cuda_bf16.h>

// Shapes: anchors (N=1024,2) f32; gt_boxes (B=128, M=256, 4) f32.
// Output f32: [matches (B*M) | ious (B,N,M)].
#define N_ANCH 1024
#define B_     128
#define M_     256

#define M_PER_CTA 32
#define NQ        8                  // m-quads per CTA: warp covers 128B/row
#define NCH       32                 // anchor chunks per CTA
#define CH        (N_ANCH / NCH)     // 32 anchors per chunk
#define NTHREADS  (NQ * NCH)         // 256

typedef unsigned long long u64;

// ---- packed f32x2 helpers (sm_103a; PTX-only; min.f32x2 does NOT exist) ----
__device__ __forceinline__ u64 pk(float lo, float hi) {
    u64 d; asm("mov.b64 %0, {%1, %2};" : "=l"(d) : "f"(lo), "f"(hi)); return d;
}
__device__ __forceinline__ void upk(u64 v, float& lo, float& hi) {
    asm("mov.b64 {%0, %1}, %2;" : "=f"(lo), "=f"(hi) : "l"(v));
}
__device__ __forceinline__ u64 mul2(u64 a, u64 b) {
    u64 d; asm("mul.rn.f32x2 %0, %1, %2;" : "=l"(d) : "l"(a), "l"(b)); return d;
}
__device__ __forceinline__ u64 add2(u64 a, u64 b) {
    u64 d; asm("add.rn.f32x2 %0, %1, %2;" : "=l"(d) : "l"(a), "l"(b)); return d;
}
__device__ __forceinline__ u64 fma2(u64 a, u64 b, u64 c) {
    u64 d; asm("fma.rn.f32x2 %0, %1, %2, %3;" : "=l"(d) : "l"(a), "l"(b), "l"(c)); return d;
}
__device__ __forceinline__ float rcpa(float x) {
    float r; asm("rcp.approx.f32 %0, %1;" : "=f"(r) : "f"(x)); return r;
}
// Fused scalar-min pair -> u64: both mins + the pack in one asm block so
// ptxas can target an aligned register pair directly (no separate MOVs).
__device__ __forceinline__ u64 minpair(float a, float x, float y) {
    u64 d;
    asm("{\n\t"
        ".reg .f32 lo, hi;\n\t"
        "min.f32 lo, %1, %2;\n\t"
        "min.f32 hi, %1, %3;\n\t"
        "mov.b64 %0, {lo, hi};\n\t"
        "}"
        : "=l"(d) : "f"(a), "f"(x), "f"(y));
    return d;
}

// Packed correctly-rounded q = x / (s - x): exact ptxas div.rn fast path
// (rcp + Newton + residual fixup). Operands always normal / well-scaled
// (x in [2.5e-3,1], s-x in [2.5e-3,2]) so the slow path can't trip:
// bit-identical to IEEE div.rn -> rel_err stays 0, argmax exact.
__device__ __forceinline__ u64 iou_div2(u64 x, u64 s) {
    const u64 NEG1 = 0xBF800000BF800000ULL;
    const u64 ONE  = 0x3F8000003F800000ULL;
    u64 y  = fma2(x, NEG1, s);                // uni = s - x
    u64 ny = mul2(y, NEG1);                   // -uni (exact)
    float y0, y1; upk(y, y0, y1);
    u64 r  = pk(rcpa(y0), rcpa(y1));
    u64 e  = fma2(ny, r, ONE);
    r      = fma2(r, e, r);
    u64 q  = mul2(x, r);
    u64 rem = fma2(ny, q, x);
    return fma2(rem, r, q);
}

// R4/R8 geometry (proven optimum): grid (B, M/32) = 1024 CTAs, block 256,
// natural regs, unroll 4. This round: conflict-free [i][ch] smem transpose.
// OLD layout s[ch*32+i]: the warp's 4 ch values sit 256B apart -> one bank,
// 4-way conflict on EVERY inner-loop LDS. NEW layout s[i*32+ch]: 8B apart,
// 4 distinct banks + 8-lane broadcast -> conflict-free.
__global__ void __launch_bounds__(NTHREADS)
matcher_kernel(const float* __restrict__ anchors,
               const float* __restrict__ gt,
               float* __restrict__ matches,
               float* __restrict__ ious)
{
    __shared__ float2 sWH[CH * NCH];         // {aw,ah}  at [i][ch]  8 KB
    __shared__ u64    sAZ[CH * NCH];         // {az,az}  at [i][ch]  8 KB
    __shared__ float  sPm[NCH][M_PER_CTA];   // per-chunk best iou   4 KB
    __shared__ int    sPi[NCH][M_PER_CTA];   // per-chunk best n     4 KB

    const int tid = threadIdx.x;
    const int mq  = tid & (NQ - 1);
    const int ch  = tid >> 3;
    const int b     = blockIdx.x;
    const int mbase = blockIdx.y * M_PER_CTA;
    const int m0    = mbase + 4 * mq;

    // Stage anchors transposed. Centered boxes => iw = min(aw,gw) bitwise
    // (0.5w exact in fp32; clips dead since 0.05 <= sizes <= 1.0).
    for (int n = tid; n < N_ANCH; n += NTHREADS) {
        const float2 a = reinterpret_cast<const float2*>(anchors)[n];
        const int slot = (n & (CH - 1)) * NCH + (n >> 5);   // [i][ch]
        sWH[slot] = a;
        const float az = a.x * a.y;
        sAZ[slot] = pk(az, az);
    }
    __syncthreads();

    float gw[4], gh[4], aB[4];
    #pragma unroll
    for (int j = 0; j < 4; j++) {
        const float4 g = reinterpret_cast<const float4*>(gt)[b * M_ + m0 + j];
        gw[j] = g.z - g.x;
        gh[j] = g.w - g.y;
        aB[j] = gw[j] * gh[j];
    }
    const u64 aB01 = pk(aB[0], aB[1]);
    const u64 aB23 = pk(aB[2], aB[3]);

    float best[4]  = {-1.0f, -1.0f, -1.0f, -1.0f};
    int   bestn[4] = {0, 0, 0, 0};

    // Indexed stores: compile-time offsets folded into STG [R+imm].
    ulonglong2* pp = reinterpret_cast<ulonglong2*>(
        ious + (size_t)b * N_ANCH * M_ + (size_t)ch * CH * M_ + m0);

    #pragma unroll 4
    for (int i = 0; i < CH; i++) {
        const float2 a  = sWH[i * NCH + ch];
        const u64    az = sAZ[i * NCH + ch];
        const u64 iw01 = minpair(a.x, gw[0], gw[1]);
        const u64 ih01 = minpair(a.y, gh[0], gh[1]);
        const u64 iw23 = minpair(a.x, gw[2], gw[3]);
        const u64 ih23 = minpair(a.y, gh[2], gh[3]);
        const u64 x01  = mul2(iw01, ih01);          // inter
        const u64 x23  = mul2(iw23, ih23);
        const u64 s01  = add2(az, aB01);            // area_a + area_b
        const u64 s23  = add2(az, aB23);
        const u64 q01  = iou_div2(x01, s01);
        const u64 q23  = iou_div2(x23, s23);

        ulonglong2 st; st.x = q01; st.y = q23;
        pp[(size_t)i * (M_ / 4)] = st;

        float r0, r1, r2, r3;
        upk(q01, r0, r1); upk(q23, r2, r3);
        if (r0 > best[0]) { best[0] = r0; bestn[0] = i; }
        if (r1 > best[1]) { best[1] = r1; bestn[1] = i; }
        if (r2 > best[2]) { best[2] = r2; bestn[2] = i; }
        if (r3 > best[3]) { best[3] = r3; bestn[3] = i; }
    }

    #pragma unroll
    for (int j = 0; j < 4; j++) {
        sPm[ch][4 * mq + j] = best[j];
        sPi[ch][4 * mq + j] = ch * CH + bestn[j];
    }
    __syncthreads();

    // Fold chunks ascending, strict-greater: first-occurring max wins,
    // matching jnp.argmax exactly.
    if (tid < M_PER_CTA) {
        float bv = sPm[0][tid];
        int   bi = sPi[0][tid];
        #pragma unroll
        for (int c = 1; c < NCH; c++) {
            const float v = sPm[c][tid];
            if (v > bv) { bv = v; bi = sPi[c][tid]; }
        }
        matches[b * M_ + mbase + tid] = (float)bi;
    }
}

extern "C" void kernel_launch(void* const* d_in, const int* in_sizes, int n_in,
                              void* d_out, int out_size)
{
    const float* anchors = (const float*)d_in[0];
    const float* gt      = (const float*)d_in[1];
    float* out = (float*)d_out;

    const size_t ious_elems = (size_t)B_ * N_ANCH * M_;
    const size_t ious_off   = (size_t)out_size - ious_elems;

    matcher_kernel<<<dim3(B_, M_ / M_PER_CTA), NTHREADS>>>(
        anchors, gt, out, out + ious_off);
}

// round 14
// speedup vs baseline: 1.0838x; 1.0838x over previous
#include <cuda_runtime.h>
#include <cuda_bf16.h>

// Shapes: anchors (N=1024,2) f32; gt_boxes (B=128, M=256, 4) f32.
// Output f32: [matches (B*M) | ious (B,N,M)].
#define N_ANCH 1024
#define B_     128
#define M_     256

#define M_PER_CTA 32
#define NQ        8                  // m-quads per CTA: warp covers 128B/row
#define NCH       32                 // anchor chunks per CTA
#define CH        (N_ANCH / NCH)     // 32 anchors per chunk
#define NTHREADS  (NQ * NCH)         // 256

typedef unsigned long long u64;

// ---- packed f32x2 helpers (sm_103a; PTX-only; min.f32x2 does NOT exist) ----
__device__ __forceinline__ u64 pk(float lo, float hi) {
    u64 d; asm("mov.b64 %0, {%1, %2};" : "=l"(d) : "f"(lo), "f"(hi)); return d;
}
__device__ __forceinline__ void upk(u64 v, float& lo, float& hi) {
    asm("mov.b64 {%0, %1}, %2;" : "=f"(lo), "=f"(hi) : "l"(v));
}
__device__ __forceinline__ u64 mul2(u64 a, u64 b) {
    u64 d; asm("mul.rn.f32x2 %0, %1, %2;" : "=l"(d) : "l"(a), "l"(b)); return d;
}
__device__ __forceinline__ u64 add2(u64 a, u64 b) {
    u64 d; asm("add.rn.f32x2 %0, %1, %2;" : "=l"(d) : "l"(a), "l"(b)); return d;
}
__device__ __forceinline__ u64 fma2(u64 a, u64 b, u64 c) {
    u64 d; asm("fma.rn.f32x2 %0, %1, %2, %3;" : "=l"(d) : "l"(a), "l"(b), "l"(c)); return d;
}
__device__ __forceinline__ float rcpa(float x) {
    float r; asm("rcp.approx.f32 %0, %1;" : "=f"(r) : "f"(x)); return r;
}

// Packed correctly-rounded q = x / (s - x): exact ptxas div.rn fast path
// (rcp + Newton + residual fixup). Operands always normal / well-scaled
// (x in [2.5e-3,1], s-x in [2.5e-3,2]) so the slow path can't trip:
// bit-identical to IEEE div.rn -> rel_err stays 0 on the ious output.
__device__ __forceinline__ u64 iou_div2(u64 x, u64 s) {
    const u64 NEG1 = 0xBF800000BF800000ULL;
    const u64 ONE  = 0x3F8000003F800000ULL;
    u64 y  = fma2(x, NEG1, s);                // uni = s - x
    u64 ny = mul2(y, NEG1);                   // -uni (exact)
    float y0, y1; upk(y, y0, y1);
    u64 r  = pk(rcpa(y0), rcpa(y1));
    u64 e  = fma2(ny, r, ONE);
    r      = fma2(r, e, r);
    u64 q  = mul2(x, r);
    u64 rem = fma2(ny, q, x);
    return fma2(rem, r, q);
}

// R8 body; hot loop tracks best VALUES only (4 FMNMX, no index SELs).
// Index recovery reads the already-written ious back from global memory
// (intra-CTA global writes are visible across __syncthreads), taking the
// first element bit-equal to the chunk max. No recomputation -> no
// contraction hazard (R13 lesson: recompute paths get FFMA-contracted).
__global__ void __launch_bounds__(NTHREADS)
matcher_kernel(const float* __restrict__ anchors,
               const float* __restrict__ gt,
               float* __restrict__ matches,
               float* __restrict__ ious)
{
    __shared__ float2 sWH[N_ANCH];           // {aw, ah}           8 KB
    __shared__ float  sPm[NCH][M_PER_CTA];   // per-chunk best iou 4 KB

    const int tid = threadIdx.x;
    const int mq  = tid & (NQ - 1);
    const int ch  = tid >> 3;
    const int b     = blockIdx.x;
    const int mbase = blockIdx.y * M_PER_CTA;
    const int m0    = mbase + 4 * mq;

    // Stage anchor widths/heights once; area recomputed per iter with one
    // FMUL. Centered boxes => iw = min(aw,gw) bitwise (0.5w exact in fp32;
    // clips dead since 0.05 <= sizes <= 1.0).
    for (int i = tid; i < N_ANCH; i += NTHREADS) {
        sWH[i] = reinterpret_cast<const float2*>(anchors)[i];
    }
    __syncthreads();

    float gw[4], gh[4], aB[4];
    #pragma unroll
    for (int j = 0; j < 4; j++) {
        const float4 g = reinterpret_cast<const float4*>(gt)[b * M_ + m0 + j];
        gw[j] = g.z - g.x;
        gh[j] = g.w - g.y;
        aB[j] = gw[j] * gh[j];
    }
    const u64 aB01 = pk(aB[0], aB[1]);
    const u64 aB23 = pk(aB[2], aB[3]);

    float best[4] = {-1.0f, -1.0f, -1.0f, -1.0f};

    // Indexed stores: compile-time offsets folded into STG [R+imm].
    ulonglong2* pp = reinterpret_cast<ulonglong2*>(
        ious + (size_t)b * N_ANCH * M_ + (size_t)ch * CH * M_ + m0);

    #pragma unroll 4
    for (int i = 0; i < CH; i++) {
        const float2 a   = sWH[ch * CH + i];
        const float  azs = a.x * a.y;
        const u64    az  = pk(azs, azs);
        const u64 iw01 = pk(fminf(a.x, gw[0]), fminf(a.x, gw[1]));
        const u64 ih01 = pk(fminf(a.y, gh[0]), fminf(a.y, gh[1]));
        const u64 iw23 = pk(fminf(a.x, gw[2]), fminf(a.x, gw[3]));
        const u64 ih23 = pk(fminf(a.y, gh[2]), fminf(a.y, gh[3]));
        const u64 x01  = mul2(iw01, ih01);          // inter
        const u64 x23  = mul2(iw23, ih23);
        const u64 s01  = add2(az, aB01);            // area_a + area_b
        const u64 s23  = add2(az, aB23);
        const u64 q01  = iou_div2(x01, s01);
        const u64 q23  = iou_div2(x23, s23);

        ulonglong2 st; st.x = q01; st.y = q23;
        pp[(size_t)i * (M_ / 4)] = st;

        float r0, r1, r2, r3;
        upk(q01, r0, r1); upk(q23, r2, r3);
        best[0] = fmaxf(best[0], r0);               // value-only: 1 FMNMX each
        best[1] = fmaxf(best[1], r1);
        best[2] = fmaxf(best[2], r2);
        best[3] = fmaxf(best[3], r3);
    }

    #pragma unroll
    for (int j = 0; j < 4; j++)
        sPm[ch][4 * mq + j] = best[j];
    __syncthreads();

    // Fold + index recovery (32 threads, one per m).
    if (tid < M_PER_CTA) {
        const int m = mbase + tid;

        // Global max and FIRST chunk attaining it (strict > ascending:
        // earlier chunks all have max < bv, preserving jnp first-max).
        float bv = sPm[0][tid];
        int   bc = 0;
        #pragma unroll
        for (int c = 1; c < NCH; c++) {
            const float v = sPm[c][tid];
            if (v > bv) { bv = v; bc = c; }
        }

        // Read the winning chunk's 32 stored ious back; first bit-equal
        // element is the argmax. Guaranteed hit: bv is fmaxf over exactly
        // these stored values.
        const float* src = ious + (size_t)b * N_ANCH * M_
                                + (size_t)bc * CH * M_ + m;
        int p = CH - 1;
        #pragma unroll 8
        for (int i = CH - 1; i >= 0; i--) {         // descending: keep FIRST
            if (src[(size_t)i * M_] == bv) p = i;
        }
        matches[b * M_ + m] = (float)(bc * CH + p);
    }
}

extern "C" void kernel_launch(void* const* d_in, const int* in_sizes, int n_in,
                              void* d_out, int out_size)
{
    const float* anchors = (const float*)d_in[0];
    const float* gt      = (const float*)d_in[1];
    float* out = (float*)d_out;

    const size_t ious_elems = (size_t)B_ * N_ANCH * M_;
    const size_t ious_off   = (size_t)out_size - ious_elems;

    matcher_kernel<<<dim3(B_, M_ / M_PER_CTA), NTHREADS>>>(
        anchors, gt, out, out + ious_off);
}

// round 15
// speedup vs baseline: 1.1393x; 1.0512x over previous
#include <cuda_runtime.h>
#include <cuda_bf16.h>

// Shapes: anchors (N=1024,2) f32; gt_boxes (B=128, M=256, 4) f32.
// Output f32: [matches (B*M) | ious (B,N,M)].
#define N_ANCH 1024
#define B_     128
#define M_     256

#define M_PER_CTA 32
#define NQ        8                  // m-quads per CTA: warp covers 128B/row
#define NCH       32                 // anchor chunks per CTA
#define CH        (N_ANCH / NCH)     // 32 anchors per chunk (== warp size)
#define NTHREADS  (NQ * NCH)         // 256

typedef unsigned long long u64;

// ---- packed f32x2 helpers (sm_103a; PTX-only; min.f32x2 does NOT exist) ----
__device__ __forceinline__ u64 pk(float lo, float hi) {
    u64 d; asm("mov.b64 %0, {%1, %2};" : "=l"(d) : "f"(lo), "f"(hi)); return d;
}
__device__ __forceinline__ void upk(u64 v, float& lo, float& hi) {
    asm("mov.b64 {%0, %1}, %2;" : "=f"(lo), "=f"(hi) : "l"(v));
}
__device__ __forceinline__ u64 mul2(u64 a, u64 b) {
    u64 d; asm("mul.rn.f32x2 %0, %1, %2;" : "=l"(d) : "l"(a), "l"(b)); return d;
}
__device__ __forceinline__ u64 add2(u64 a, u64 b) {
    u64 d; asm("add.rn.f32x2 %0, %1, %2;" : "=l"(d) : "l"(a), "l"(b)); return d;
}
__device__ __forceinline__ u64 fma2(u64 a, u64 b, u64 c) {
    u64 d; asm("fma.rn.f32x2 %0, %1, %2, %3;" : "=l"(d) : "l"(a), "l"(b), "l"(c)); return d;
}
__device__ __forceinline__ float rcpa(float x) {
    float r; asm("rcp.approx.f32 %0, %1;" : "=f"(r) : "f"(x)); return r;
}

// Packed correctly-rounded q = x / (s - x): exact ptxas div.rn fast path
// (rcp + Newton + residual fixup). Operands always normal / well-scaled
// (x in [2.5e-3,1], s-x in [2.5e-3,2]) so the slow path can't trip:
// bit-identical to IEEE div.rn -> rel_err stays 0 on the ious output.
__device__ __forceinline__ u64 iou_div2(u64 x, u64 s) {
    const u64 NEG1 = 0xBF800000BF800000ULL;
    const u64 ONE  = 0x3F8000003F800000ULL;
    u64 y  = fma2(x, NEG1, s);                // uni = s - x
    u64 ny = mul2(y, NEG1);                   // -uni (exact)
    float y0, y1; upk(y, y0, y1);
    u64 r  = pk(rcpa(y0), rcpa(y1));
    u64 e  = fma2(ny, r, ONE);
    r      = fma2(r, e, r);
    u64 q  = mul2(x, r);
    u64 rem = fma2(ny, q, x);
    return fma2(rem, r, q);
}

// R13 hot loop (value-only argmax, 40 regs, best kernel time) + NEW warp-
// parallel fold/recovery: all 8 warps, shfl-max + ballot, one LDG per lane.
// First-chunk-then-first-position == global first max == jnp.argmax.
__global__ void __launch_bounds__(NTHREADS)
matcher_kernel(const float* __restrict__ anchors,
               const float* __restrict__ gt,
               float* __restrict__ matches,
               float* __restrict__ ious)
{
    __shared__ float2 sWH[N_ANCH];             // {aw, ah}            8 KB
    __shared__ float  sPm[M_PER_CTA][NCH + 1]; // best iou [m][chunk] ~4 KB

    const int tid = threadIdx.x;
    const int mq  = tid & (NQ - 1);
    const int ch  = tid >> 3;
    const int b     = blockIdx.x;
    const int mbase = blockIdx.y * M_PER_CTA;
    const int m0    = mbase + 4 * mq;

    // Stage anchor widths/heights once; area recomputed per iter with one
    // FMUL. Centered boxes => iw = min(aw,gw) bitwise (0.5w exact in fp32;
    // clips dead since 0.05 <= sizes <= 1.0).
    for (int i = tid; i < N_ANCH; i += NTHREADS) {
        sWH[i] = reinterpret_cast<const float2*>(anchors)[i];
    }
    __syncthreads();

    float gw[4], gh[4], aB[4];
    #pragma unroll
    for (int j = 0; j < 4; j++) {
        const float4 g = reinterpret_cast<const float4*>(gt)[b * M_ + m0 + j];
        gw[j] = g.z - g.x;
        gh[j] = g.w - g.y;
        aB[j] = gw[j] * gh[j];
    }
    const u64 aB01 = pk(aB[0], aB[1]);
    const u64 aB23 = pk(aB[2], aB[3]);

    float best[4] = {-1.0f, -1.0f, -1.0f, -1.0f};

    // Indexed stores: compile-time offsets folded into STG [R+imm].
    ulonglong2* pp = reinterpret_cast<ulonglong2*>(
        ious + (size_t)b * N_ANCH * M_ + (size_t)ch * CH * M_ + m0);

    #pragma unroll 4
    for (int i = 0; i < CH; i++) {
        const float2 a   = sWH[ch * CH + i];
        const float  azs = a.x * a.y;
        const u64    az  = pk(azs, azs);
        const u64 iw01 = pk(fminf(a.x, gw[0]), fminf(a.x, gw[1]));
        const u64 ih01 = pk(fminf(a.y, gh[0]), fminf(a.y, gh[1]));
        const u64 iw23 = pk(fminf(a.x, gw[2]), fminf(a.x, gw[3]));
        const u64 ih23 = pk(fminf(a.y, gh[2]), fminf(a.y, gh[3]));
        const u64 x01  = mul2(iw01, ih01);          // inter
        const u64 x23  = mul2(iw23, ih23);
        const u64 s01  = add2(az, aB01);            // area_a + area_b
        const u64 s23  = add2(az, aB23);
        const u64 q01  = iou_div2(x01, s01);
        const u64 q23  = iou_div2(x23, s23);

        ulonglong2 st; st.x = q01; st.y = q23;
        pp[(size_t)i * (M_ / 4)] = st;

        float r0, r1, r2, r3;
        upk(q01, r0, r1); upk(q23, r2, r3);
        best[0] = fmaxf(best[0], r0);               // value-only: 1 FMNMX each
        best[1] = fmaxf(best[1], r1);
        best[2] = fmaxf(best[2], r2);
        best[3] = fmaxf(best[3], r3);
    }

    #pragma unroll
    for (int j = 0; j < 4; j++)
        sPm[4 * mq + j][ch] = best[j];
    __syncthreads();

    // Warp-parallel fold + index recovery: warp w owns m-rows 4w..4w+3.
    const int wid  = tid >> 5;
    const int lane = tid & 31;
    #pragma unroll
    for (int k = 0; k < 4; k++) {
        const int mm = wid * 4 + k;
        const float v = sPm[mm][lane];              // lane = chunk (conflict-free)

        // Warp max (butterfly). All lanes end with the global max bv.
        float bv = v;
        #pragma unroll
        for (int off = 16; off; off >>= 1)
            bv = fmaxf(bv, __shfl_xor_sync(0xffffffffu, bv, off));

        // First chunk attaining bv (lowest set bit = smallest chunk id).
        const unsigned cm = __ballot_sync(0xffffffffu, v == bv);
        const int bc = __ffs(cm) - 1;

        // Read the winning chunk's stored ious (lane = position in chunk);
        // first bit-equal element is the argmax. Guaranteed hit: bv is the
        // max over exactly these stored values (no recomputation).
        const int m = mbase + mm;
        const float val = ious[(size_t)b * N_ANCH * M_
                               + (size_t)(bc * CH + lane) * M_ + m];
        const unsigned pm = __ballot_sync(0xffffffffu, val == bv);
        const int p = __ffs(pm) - 1;

        if (lane == 0)
            matches[b * M_ + m] = (float)(bc * CH + p);
    }
}

extern "C" void kernel_launch(void* const* d_in, const int* in_sizes, int n_in,
                              void* d_out, int out_size)
{
    const float* anchors = (const float*)d_in[0];
    const float* gt      = (const float*)d_in[1];
    float* out = (float*)d_out;

    const size_t ious_elems = (size_t)B_ * N_ANCH * M_;
    const size_t ious_off   = (size_t)out_size - ious_elems;

    matcher_kernel<<<dim3(B_, M_ / M_PER_CTA), NTHREADS>>>(
        anchors, gt, out, out + ious_off);
}